// round 12
// baseline (speedup 1.0000x reference)
#include <cuda_runtime.h>
#include <cuda_bf16.h>
#include <cstdint>
#include <cstddef>

// Problem constants
#define NUM_STATE 2048
#define BATCH     4096

// ---------------------------------------------------------------------------
// Scratch (device globals; no cudaMalloc allowed)
// ---------------------------------------------------------------------------
__device__ __align__(16) __nv_bfloat16 g_alphaB[(size_t)BATCH * NUM_STATE];     // 16 MB
__device__ __align__(16) __nv_bfloat16 g_matT[(size_t)NUM_STATE * NUM_STATE];   // 8 MB, matT[t][s] = mat[s][t]
__device__ float g_rmax[NUM_STATE];
__device__ float g_rinv[NUM_STATE];

// ---------------------------------------------------------------------------
// Helpers
// ---------------------------------------------------------------------------
__device__ __forceinline__ uint32_t smem_u32(const void* p) {
    uint32_t a;
    asm("{ .reg .u64 t; cvta.to.shared.u64 t, %1; cvt.u32.u64 %0, t; }" : "=r"(a) : "l"(p));
    return a;
}

#define SWZ128(off) ((off) ^ (((off) >> 3) & 0x70))

__device__ __forceinline__ void cp_async16(uint32_t s, const void* g) {
    asm volatile("cp.async.cg.shared.global [%0], [%1], 16;" :: "r"(s), "l"(g) : "memory");
}
#define CP_COMMIT() asm volatile("cp.async.commit_group;" ::: "memory")
template <int N>
__device__ __forceinline__ void cp_wait() {
    asm volatile("cp.async.wait_group %0;" :: "n"(N) : "memory");
}

__device__ __forceinline__ void ldsm4(uint32_t* r, uint32_t addr) {
    asm volatile("ldmatrix.sync.aligned.m8n8.x4.shared.b16 {%0,%1,%2,%3}, [%4];"
                 : "=r"(r[0]), "=r"(r[1]), "=r"(r[2]), "=r"(r[3]) : "r"(addr));
}

__device__ __forceinline__ void mma_bf16(float* c, const uint32_t* a,
                                         uint32_t b0, uint32_t b1) {
    asm volatile(
        "mma.sync.aligned.m16n8k16.row.col.f32.bf16.bf16.f32 "
        "{%0,%1,%2,%3}, {%4,%5,%6,%7}, {%8,%9}, {%0,%1,%2,%3};"
        : "+f"(c[0]), "+f"(c[1]), "+f"(c[2]), "+f"(c[3])
        : "r"(a[0]), "r"(a[1]), "r"(a[2]), "r"(a[3]), "r"(b0), "r"(b1));
}

// ---------------------------------------------------------------------------
// Alpha fp32 -> bf16 conversion chunk: one block converts 8192 contiguous
// elements (256 threads x 8 float4, all loads independent -> MLP 8).
// ---------------------------------------------------------------------------
static constexpr int CVT_CHUNK = 8192;
static constexpr int CVT_CHUNKS_TOTAL = (BATCH * NUM_STATE) / CVT_CHUNK;  // 1024
static constexpr int CVT1_CHUNKS = 600;                                    // in prep1
static constexpr int CVT2_CHUNKS = CVT_CHUNKS_TOTAL - CVT1_CHUNKS;         // 424 in prep2
static constexpr int STATS_BLOCKS = NUM_STATE / 2;                         // 1024 (2 rows/block)
static constexpr int BUILD_BLOCKS = (NUM_STATE / 32) * (NUM_STATE / 64);   // 2048 (32s x 64t)

__device__ __forceinline__ void cvt_alpha_chunk(const float* __restrict__ a, int cb) {
    const size_t base = (size_t)cb * CVT_CHUNK + threadIdx.x * 4;
    float4 v[8];
    #pragma unroll
    for (int j = 0; j < 8; j++)
        v[j] = *reinterpret_cast<const float4*>(a + base + (size_t)j * 1024);
    #pragma unroll
    for (int j = 0; j < 8; j++) {
        __nv_bfloat162 p0 = __floats2bfloat162_rn(v[j].x, v[j].y);
        __nv_bfloat162 p1 = __floats2bfloat162_rn(v[j].z, v[j].w);
        uint2 w;
        w.x = *reinterpret_cast<uint32_t*>(&p0);
        w.y = *reinterpret_cast<uint32_t*>(&p1);
        *reinterpret_cast<uint2*>(&g_alphaB[base + (size_t)j * 1024]) = w;
    }
}

// ---------------------------------------------------------------------------
// Prep kernel 1: [blocks 0..1023] softmax stats for TWO rows per block
// (16 independent LDGs/thread, per-row reduction partition identical to the
// single-row version -> bit-identical results); [blocks 1024..] cvt chunks.
// ---------------------------------------------------------------------------
__global__ __launch_bounds__(256) void prep1_kernel(const float* __restrict__ utm,
                                                    const float* __restrict__ alpha) {
    if (blockIdx.x >= STATS_BLOCKS) {
        cvt_alpha_chunk(alpha, blockIdx.x - STATS_BLOCKS);
        return;
    }
    const int tid = threadIdx.x;
    const int base = tid * 8;
    const int s0 = blockIdx.x * 2;

    __shared__ float red[16];
    __shared__ float s_mx[2];

    // Load both rows' elements up front (MLP 16)
    float v[2][8];
    #pragma unroll
    for (int h = 0; h < 2; h++) {
        const float* row = utm + (size_t)(s0 + h) * (NUM_STATE - 1);
        #pragma unroll
        for (int j = 0; j < 8; j++)
            v[h][j] = (base + j < NUM_STATE - 1) ? row[base + j] : -3.4e38f;
    }

    // Max reduction, both rows
    #pragma unroll
    for (int h = 0; h < 2; h++) {
        float mx = v[h][0];
        #pragma unroll
        for (int j = 1; j < 8; j++) mx = fmaxf(mx, v[h][j]);
        #pragma unroll
        for (int o = 16; o; o >>= 1) mx = fmaxf(mx, __shfl_xor_sync(0xffffffffu, mx, o));
        if ((tid & 31) == 0) red[(tid >> 5) + h * 8] = mx;
    }
    __syncthreads();
    if (tid < 2) {
        float m = red[tid * 8];
        #pragma unroll
        for (int i = 1; i < 8; i++) m = fmaxf(m, red[tid * 8 + i]);
        s_mx[tid] = m;
    }
    __syncthreads();

    // Sum reduction, both rows
    #pragma unroll
    for (int h = 0; h < 2; h++) {
        const float m = s_mx[h];
        float sm = 0.f;
        #pragma unroll
        for (int j = 0; j < 8; j++)
            if (base + j < NUM_STATE - 1) sm += __expf(v[h][j] - m);
        #pragma unroll
        for (int o = 16; o; o >>= 1) sm += __shfl_xor_sync(0xffffffffu, sm, o);
        if ((tid & 31) == 0) red[(tid >> 5) + h * 8] = sm;
    }
    __syncthreads();
    if (tid < 2) {
        float t = 0.f;
        #pragma unroll
        for (int i = 0; i < 8; i++) t += red[tid * 8 + i];
        g_rmax[s0 + tid] = s_mx[tid];
        g_rinv[s0 + tid] = 1.0f / t;
    }
}

// ---------------------------------------------------------------------------
// Prep kernel 2: [blocks 0..2047] build matT tiles of 32 s x 64 t;
// [2048..] remaining cvt chunks.
// mat[s][t] = (t==s) ? 0 : exp(u[s][t-(t>s)] - max[s]) * inv[s]
// ---------------------------------------------------------------------------
__global__ __launch_bounds__(256) void prep2_kernel(const float* __restrict__ utm,
                                                    const float* __restrict__ alpha) {
    if (blockIdx.x >= BUILD_BLOCKS) {
        cvt_alpha_chunk(alpha, CVT1_CHUNKS + (int)blockIdx.x - BUILD_BLOCKS);
        return;
    }
    const int s0 = (blockIdx.x & 63) * 32;
    const int t0 = (blockIdx.x >> 6) * 64;
    const int tl = threadIdx.x;
    const int tx = tl & 31;        // -> s
    const int ty = tl >> 5;        // -> t (x8)

    // su[sy][cx] = u[s0+sy][t0-1+cx], cx in [0,65): covers c in [t0-1, t0+63]
    __shared__ float su[32][66];

    for (int i = tl; i < 32 * 65; i += 256) {
        const int sy = i / 65;
        const int cx = i % 65;
        const int c = t0 - 1 + cx;
        su[sy][cx] = (c >= 0 && c < NUM_STATE - 1)
                       ? utm[(size_t)(s0 + sy) * (NUM_STATE - 1) + c] : 0.f;
    }
    __syncthreads();

    const int s = s0 + tx;
    const float mx = g_rmax[s];
    const float inv = g_rinv[s];

    #pragma unroll
    for (int k = 0; k < 8; k++) {
        const int yy = ty + 8 * k;      // 0..63
        const int t = t0 + yy;
        float v;
        if (t == s) {
            v = 0.f;
        } else {
            const int cx = yy + 1 - (t > s);   // = (t - (t>s)) - (t0-1)
            v = __expf(su[tx][cx] - mx) * inv;
        }
        g_matT[(size_t)t * NUM_STATE + s] = __float2bfloat16(v);
    }
}

// ---------------------------------------------------------------------------
// GEMM: mma.sync bf16, C[4096,2048] = A @ matT^T   (frozen: R11 config is at
// the legacy-HMMA issue floor, ~980 cyc/kit ~= 128 HMMA/SMSP x rt 8).
// CTA tile 64x128x64 -> 1024 tiles (tail 1.2%); 3-stage cp.async; 2 CTAs/SM.
// ---------------------------------------------------------------------------
static constexpr int BM = 64, BN = 128, BK = 64, STAGES = 3;
static constexpr int KITERS = NUM_STATE / BK;                       // 32
static constexpr int A_TILE_BYTES = BM * BK * 2;                    // 8192
static constexpr int B_TILE_BYTES = BN * BK * 2;                    // 16384
static constexpr int STAGE_BYTES = A_TILE_BYTES + B_TILE_BYTES;     // 24576
static constexpr int DYN_SMEM = STAGES * STAGE_BYTES + 1024;        // 74752
static constexpr int GEMM_TILES = (BATCH / BM) * (NUM_STATE / BN);  // 1024

__global__ __launch_bounds__(256, 2) void gemm_kernel(float* __restrict__ out) {
    extern __shared__ char dsm[];
    const uint32_t dyn_base = (smem_u32(dsm) + 1023u) & ~1023u;

    const int tid = threadIdx.x;
    const int wid = tid >> 5;
    const int lane = tid & 31;

    const int tile = blockIdx.x;
    const int n0 = (tile & 15) * BN;
    const int m0 = (tile >> 4) * BM;

    const int warp_m = wid & 1;           // 2 slices of 32 rows
    const int warp_n = wid >> 1;          // 4 slices of 32 cols

    const int lrow = lane & 15;
    const int lcol16 = (lane >> 4) & 1;

    uint32_t aswz[2], bswz[2];
    #pragma unroll
    for (int mi = 0; mi < 2; mi++)
        aswz[mi] = SWZ128((uint32_t)((warp_m * 32 + mi * 16 + lrow) * 128 + lcol16 * 16));
    #pragma unroll
    for (int nj = 0; nj < 2; nj++)
        bswz[nj] = SWZ128((uint32_t)((warp_n * 32 + nj * 16 + lrow) * 128 + lcol16 * 16));

    auto load_stage = [&](int kit) {
        const int buf = kit % STAGES;
        const uint32_t sA = dyn_base + buf * STAGE_BYTES;
        const uint32_t sB = sA + A_TILE_BYTES;
        const int k0 = kit * BK;
        #pragma unroll
        for (int r = 0; r < 6; r++) {
            const int idx = tid + r * 256;       // 0..1535
            const int row = idx >> 3;            // 0..191: 0-63 A, 64-191 B
            const int c16 = idx & 7;
            if (row < BM) {
                const uint32_t soff = SWZ128((uint32_t)(row * 128 + c16 * 16));
                cp_async16(sA + soff,
                           &g_alphaB[(size_t)(m0 + row) * NUM_STATE + k0 + c16 * 8]);
            } else {
                const int rb = row - BM;
                const uint32_t soff = SWZ128((uint32_t)(rb * 128 + c16 * 16));
                cp_async16(sB + soff,
                           &g_matT[(size_t)(n0 + rb) * NUM_STATE + k0 + c16 * 8]);
            }
        }
    };

    float c[2][4][4];
    #pragma unroll
    for (int i = 0; i < 2; i++)
        #pragma unroll
        for (int j = 0; j < 4; j++)
            #pragma unroll
            for (int k = 0; k < 4; k++) c[i][j][k] = 0.f;

    uint32_t af[2][4], bf[2][4];

    auto ldsm_ks = [&](uint32_t sA, uint32_t sB, int ks) {
        const uint32_t kx = (uint32_t)(ks << 5);
        #pragma unroll
        for (int mi = 0; mi < 2; mi++) ldsm4(af[mi], sA + (aswz[mi] ^ kx));
        #pragma unroll
        for (int nj = 0; nj < 2; nj++) ldsm4(bf[nj], sB + (bswz[nj] ^ kx));
    };
    // ldmatrix x4 register layout:
    //   bf[nj][0] = (n 0-7 , k 0-7)   bf[nj][1] = (n 8-15, k 0-7)
    //   bf[nj][2] = (n 0-7 , k 8-15)  bf[nj][3] = (n 8-15, k 8-15)
    auto mma_all = [&]() {
        #pragma unroll
        for (int mi = 0; mi < 2; mi++)
            #pragma unroll
            for (int nj = 0; nj < 2; nj++) {
                mma_bf16(c[mi][nj * 2 + 0], af[mi], bf[nj][0], bf[nj][2]);
                mma_bf16(c[mi][nj * 2 + 1], af[mi], bf[nj][1], bf[nj][3]);
            }
    };

    #pragma unroll
    for (int i = 0; i < STAGES - 1; i++) { load_stage(i); CP_COMMIT(); }

    for (int kit = 0; kit < KITERS; kit++) {
        cp_wait<STAGES - 2>();
        __syncthreads();

        const uint32_t sA = dyn_base + (kit % STAGES) * STAGE_BYTES;
        const uint32_t sB = sA + A_TILE_BYTES;

        ldsm_ks(sA, sB, 0);
        if (kit + STAGES - 1 < KITERS) load_stage(kit + STAGES - 1);
        CP_COMMIT();   // unconditional: keeps wait_group accounting exact in the tail

        #pragma unroll
        for (int ks = 0; ks < BK / 16; ks++) {
            mma_all();
            if (ks < BK / 16 - 1) ldsm_ks(sA, sB, ks + 1);
        }
    }

    // Epilogue: direct float2 stores (warp 32x32 tile)
    const int r_base = m0 + warp_m * 32 + (lane >> 2);
    const int c_base = n0 + warp_n * 32 + (lane & 3) * 2;
    #pragma unroll
    for (int mi = 0; mi < 2; mi++) {
        #pragma unroll
        for (int ni = 0; ni < 4; ni++) {
            float* p0 = out + (size_t)(r_base + mi * 16) * NUM_STATE + c_base + ni * 8;
            float* p1 = out + (size_t)(r_base + mi * 16 + 8) * NUM_STATE + c_base + ni * 8;
            *reinterpret_cast<float2*>(p0) = make_float2(c[mi][ni][0], c[mi][ni][1]);
            *reinterpret_cast<float2*>(p1) = make_float2(c[mi][ni][2], c[mi][ni][3]);
        }
    }
}

// ---------------------------------------------------------------------------
// Launch
// ---------------------------------------------------------------------------
extern "C" void kernel_launch(void* const* d_in, const int* in_sizes, int n_in,
                              void* d_out, int out_size) {
    (void)in_sizes; (void)n_in; (void)out_size;
    // metadata order: state_embeddings(0, unused), alpha(1), context(2, unused), utm(3)
    const float* alpha = (const float*)d_in[1];
    const float* utm   = (const float*)d_in[3];
    float* out = (float*)d_out;

    cudaFuncSetAttribute(gemm_kernel, cudaFuncAttributeMaxDynamicSharedMemorySize, DYN_SMEM);

    prep1_kernel<<<STATS_BLOCKS + CVT1_CHUNKS, 256>>>(utm, alpha);
    prep2_kernel<<<BUILD_BLOCKS + CVT2_CHUNKS, 256>>>(utm, alpha);
    gemm_kernel<<<GEMM_TILES, 256, DYN_SMEM>>>(out);
}